// round 4
// baseline (speedup 1.0000x reference)
#include <cuda_runtime.h>
#include <cuda_bf16.h>
#include <cstdint>

// Problem constants
#define TT   32
#define NN   5000
#define EE   80000
#define HH   128
#define HD2  512
#define CC   10
#define NT   (TT*NN)          // 160000 total nodes

// ---------------- device scratch (static; no allocation) ----------------
__device__ int   g_deg[NT];
__device__ float g_dinv[NT];
__device__ int   g_rowstart[TT*(NN+1)];
__device__ int   g_cursor[NT];
__device__ int   g_sorted[TT*EE];
__device__ int16_t g_bufQ[(size_t)NT*HH];  // quantized h' = dinv * (x @ W)
__device__ float   g_rscale[NT];           // per-row dequant scale
__device__ float g_bufY[(size_t)NT*HH];    // layer output (fp32)
__device__ float g_partial[TT*8*HH];
__device__ float g_q[TT*HH], g_k[TT*HH], g_v[TT*HH];
__device__ float g_yr[TT*HH];

__device__ __forceinline__ float4 ld4(const float* p){ return *reinterpret_cast<const float4*>(p); }
__device__ __forceinline__ float fast_tanh(float x){ asm("tanh.approx.f32 %0, %0;" : "+f"(x)); return x; }
__device__ __forceinline__ uint32_t smem_u32(const void* p){
    uint32_t a;
    asm("{ .reg .u64 t; cvta.to.shared.u64 t, %1; cvt.u32.u64 %0, t; }" : "=r"(a) : "l"(p));
    return a;
}
__device__ __forceinline__ uint32_t pack2(__nv_bfloat16 a, __nv_bfloat16 b){
    __nv_bfloat162 t = __halves2bfloat162(a, b);
    return *reinterpret_cast<uint32_t*>(&t);
}

#define LDSM_X4(r0,r1,r2,r3, addr) \
    asm volatile("ldmatrix.sync.aligned.m8n8.x4.shared.b16 {%0,%1,%2,%3}, [%4];" \
        : "=r"(r0),"=r"(r1),"=r"(r2),"=r"(r3) : "r"(addr))
#define LDSM_X4_T(r0,r1,r2,r3, addr) \
    asm volatile("ldmatrix.sync.aligned.m8n8.x4.trans.shared.b16 {%0,%1,%2,%3}, [%4];" \
        : "=r"(r0),"=r"(r1),"=r"(r2),"=r"(r3) : "r"(addr))
#define MMA16816(d, a, b) \
    asm volatile("mma.sync.aligned.m16n8k16.row.col.f32.bf16.bf16.f32 " \
        "{%0,%1,%2,%3}, {%4,%5,%6,%7}, {%8,%9}, {%0,%1,%2,%3};" \
        : "+f"((d)[0]),"+f"((d)[1]),"+f"((d)[2]),"+f"((d)[3]) \
        : "r"((a)[0]),"r"((a)[1]),"r"((a)[2]),"r"((a)[3]), "r"((b)[0]),"r"((b)[1]))

// ---------------- setup kernels (run once per launch) ----------------
__global__ void k_init_deg(){
    int i = blockIdx.x*256 + threadIdx.x;
    if (i < NT) g_deg[i] = 1;   // self loop
}

__global__ void k_count(const int* __restrict__ ei){
    int i = blockIdx.x*256 + threadIdx.x;      // < TT*EE (exact grid)
    int t = i / EE, e = i - t*EE;
    int dst = ei[t*2*EE + EE + e];
    atomicAdd(&g_deg[t*NN + dst], 1);
}

__global__ void __launch_bounds__(256) k_scan(){
    int t = blockIdx.x, tid = threadIdx.x;
    __shared__ int sh[256];
    __shared__ int sbase;
    if (tid == 0) sbase = 0;
    __syncthreads();
    for (int c = 0; c < 20; c++){
        int idx = c*256 + tid;
        int cnt = (idx < NN) ? (g_deg[t*NN+idx] - 1) : 0;
        sh[tid] = cnt; __syncthreads();
        #pragma unroll
        for (int off = 1; off < 256; off <<= 1){
            int v = (tid >= off) ? sh[tid-off] : 0;
            __syncthreads();
            sh[tid] += v;
            __syncthreads();
        }
        int incl = sh[tid];
        int base = sbase;
        if (idx < NN){
            int ex = base + incl - cnt;
            g_rowstart[t*(NN+1)+idx] = ex;
            g_cursor[t*NN+idx] = ex;
            g_dinv[t*NN+idx] = rsqrtf((float)(cnt + 1));
        }
        __syncthreads();
        if (tid == 255) sbase = base + incl;
        __syncthreads();
    }
    if (tid == 0) g_rowstart[t*(NN+1)+NN] = sbase;  // == EE
}

__global__ void k_sort(const int* __restrict__ ei){
    int i = blockIdx.x*256 + threadIdx.x;
    int t = i / EE, e = i - t*EE;
    int src = ei[t*2*EE + e];
    int dst = ei[t*2*EE + EE + e];
    int pos = atomicAdd(&g_cursor[t*NN + dst], 1);
    g_sorted[t*EE + pos] = src;
}

// ---------------- tensor-core GEMM: h' = dinv * (X @ W), int16 quantized out ----------------
// mma.sync m16n8k16 bf16, hi/lo split: D = Ah*Bh + Al*Bh + Ah*Bl.
// CTA: 128x128; 8 warps, each 32 rows x 64 cols; K=128 in 8 steps.
// Epilogue: scale by dinv, per-row absmax (quad shfl + smem atomicMax), int16 store.
#define PADW 136
#define GEMM_SMEM (4*128*PADW*2)

__global__ void __launch_bounds__(256) k_gemm_mma(const float* __restrict__ X0,
                                                  const float* __restrict__ W,
                                                  int layer){
    extern __shared__ __align__(16) char sm_[];
    __nv_bfloat16* Ah = (__nv_bfloat16*)sm_;
    __nv_bfloat16* Al = Ah + 128*PADW;
    __nv_bfloat16* Bh = Al + 128*PADW;
    __nv_bfloat16* Bl = Bh + 128*PADW;
    __shared__ uint32_t sMax[128];
    const float* __restrict__ X = (layer == 0) ? X0 : g_bufY;
    const int tid = threadIdx.x, wid = tid >> 5, lane = tid & 31;
    const int bm = blockIdx.x * 128;

    if (tid < 128) sMax[tid] = 0u;

    // ---- fill A (X rows) and B (W, k-major) as hi/lo bf16 ----
    #pragma unroll
    for (int i = 0; i < 16; i++){
        int idx4 = tid + i*256;              // 0..4095
        int row  = idx4 >> 5;                // 0..127
        int c0   = (idx4 & 31) << 2;         // 0..124
        float4 v = ld4(X + (size_t)(bm + row)*128 + c0);
        float4 w = ld4(W + (size_t)row*128 + c0);
        __nv_bfloat16 ah0 = __float2bfloat16(v.x), ah1 = __float2bfloat16(v.y);
        __nv_bfloat16 ah2 = __float2bfloat16(v.z), ah3 = __float2bfloat16(v.w);
        __nv_bfloat16 bh0 = __float2bfloat16(w.x), bh1 = __float2bfloat16(w.y);
        __nv_bfloat16 bh2 = __float2bfloat16(w.z), bh3 = __float2bfloat16(w.w);
        uint2 avh, avl, bvh, bvl;
        avh.x = pack2(ah0, ah1); avh.y = pack2(ah2, ah3);
        bvh.x = pack2(bh0, bh1); bvh.y = pack2(bh2, bh3);
        avl.x = pack2(__float2bfloat16(v.x - __bfloat162float(ah0)),
                      __float2bfloat16(v.y - __bfloat162float(ah1)));
        avl.y = pack2(__float2bfloat16(v.z - __bfloat162float(ah2)),
                      __float2bfloat16(v.w - __bfloat162float(ah3)));
        bvl.x = pack2(__float2bfloat16(w.x - __bfloat162float(bh0)),
                      __float2bfloat16(w.y - __bfloat162float(bh1)));
        bvl.y = pack2(__float2bfloat16(w.z - __bfloat162float(bh2)),
                      __float2bfloat16(w.w - __bfloat162float(bh3)));
        int s = row*PADW + c0;
        *reinterpret_cast<uint2*>(Ah + s) = avh;
        *reinterpret_cast<uint2*>(Al + s) = avl;
        *reinterpret_cast<uint2*>(Bh + s) = bvh;
        *reinterpret_cast<uint2*>(Bl + s) = bvl;
    }
    __syncthreads();

    const int wr = (wid & 3) * 32;           // warp row base
    const int wc = (wid >> 2) * 64;          // warp col base
    const int half = wid >> 2;
    const int lhalf = (lane >> 4) << 3;

    const uint32_t aBaseH = smem_u32(Ah) + (uint32_t)(((wr + (lane & 15))*PADW + lhalf) * 2);
    const uint32_t aBaseL = aBaseH + (uint32_t)(128*PADW*2);
    const uint32_t bBaseH = smem_u32(Bh) + (uint32_t)(((lane & 15)*PADW + wc + lhalf) * 2);
    const uint32_t bBaseL = bBaseH + (uint32_t)(128*PADW*2);

    float acc[2][8][4];
    #pragma unroll
    for (int mt = 0; mt < 2; mt++)
        #pragma unroll
        for (int nt = 0; nt < 8; nt++)
            #pragma unroll
            for (int c = 0; c < 4; c++) acc[mt][nt][c] = 0.f;

    #pragma unroll
    for (int ks = 0; ks < 8; ks++){
        const uint32_t k0b  = (uint32_t)(ks*16*2);
        const uint32_t k0rb = (uint32_t)(ks*16*PADW*2);
        uint32_t ah[2][4], al[2][4], bh[8][2], bl[8][2];
        #pragma unroll
        for (int mt = 0; mt < 2; mt++){
            uint32_t aH = aBaseH + (uint32_t)(mt*16*PADW*2) + k0b;
            uint32_t aL = aBaseL + (uint32_t)(mt*16*PADW*2) + k0b;
            LDSM_X4(ah[mt][0], ah[mt][1], ah[mt][2], ah[mt][3], aH);
            LDSM_X4(al[mt][0], al[mt][1], al[mt][2], al[mt][3], aL);
        }
        #pragma unroll
        for (int p = 0; p < 4; p++){
            uint32_t bH = bBaseH + k0rb + (uint32_t)(p*16*2);
            uint32_t bL = bBaseL + k0rb + (uint32_t)(p*16*2);
            LDSM_X4_T(bh[2*p][0], bh[2*p][1], bh[2*p+1][0], bh[2*p+1][1], bH);
            LDSM_X4_T(bl[2*p][0], bl[2*p][1], bl[2*p+1][0], bl[2*p+1][1], bL);
        }
        #pragma unroll
        for (int mt = 0; mt < 2; mt++)
            #pragma unroll
            for (int nt = 0; nt < 8; nt++){
                MMA16816(acc[mt][nt], ah[mt], bh[nt]);
                MMA16816(acc[mt][nt], al[mt], bh[nt]);
                MMA16816(acc[mt][nt], ah[mt], bl[nt]);
            }
    }

    // ---- epilogue: scale by dinv, per-row absmax, int16 quantized store ----
    const int lr = lane >> 2, lq = lane & 3;
    #pragma unroll
    for (int mt = 0; mt < 2; mt++){
        int r0 = bm + wr + mt*16 + lr;
        float s0 = g_dinv[r0], s1 = g_dinv[r0 + 8];
        float m0 = 0.f, m1 = 0.f;
        #pragma unroll
        for (int nt = 0; nt < 8; nt++){
            acc[mt][nt][0] *= s0; acc[mt][nt][1] *= s0;
            acc[mt][nt][2] *= s1; acc[mt][nt][3] *= s1;
            m0 = fmaxf(m0, fmaxf(fabsf(acc[mt][nt][0]), fabsf(acc[mt][nt][1])));
            m1 = fmaxf(m1, fmaxf(fabsf(acc[mt][nt][2]), fabsf(acc[mt][nt][3])));
        }
        m0 = fmaxf(m0, __shfl_xor_sync(0xffffffffu, m0, 1));
        m0 = fmaxf(m0, __shfl_xor_sync(0xffffffffu, m0, 2));
        m1 = fmaxf(m1, __shfl_xor_sync(0xffffffffu, m1, 1));
        m1 = fmaxf(m1, __shfl_xor_sync(0xffffffffu, m1, 2));
        if (lq == 0){
            atomicMax(&sMax[wr + mt*16 + lr],     __float_as_uint(m0));
            atomicMax(&sMax[wr + mt*16 + lr + 8], __float_as_uint(m1));
        }
    }
    __syncthreads();
    #pragma unroll
    for (int mt = 0; mt < 2; mt++){
        int l0 = wr + mt*16 + lr;
        float M0 = __uint_as_float(sMax[l0]);
        float M1 = __uint_as_float(sMax[l0 + 8]);
        float inv0 = (M0 > 0.f) ? 32767.f / M0 : 0.f;
        float inv1 = (M1 > 0.f) ? 32767.f / M1 : 0.f;
        if (half == 0 && lq == 0){
            g_rscale[bm + l0]     = M0 * (1.f/32767.f);
            g_rscale[bm + l0 + 8] = M1 * (1.f/32767.f);
        }
        uint32_t* p0 = reinterpret_cast<uint32_t*>(g_bufQ + (size_t)(bm + l0)*128 + wc + lq*2);
        uint32_t* p1 = reinterpret_cast<uint32_t*>(g_bufQ + (size_t)(bm + l0 + 8)*128 + wc + lq*2);
        #pragma unroll
        for (int nt = 0; nt < 8; nt++){
            int q0 = __float2int_rn(acc[mt][nt][0]*inv0);
            int q1 = __float2int_rn(acc[mt][nt][1]*inv0);
            int q2 = __float2int_rn(acc[mt][nt][2]*inv1);
            int q3 = __float2int_rn(acc[mt][nt][3]*inv1);
            q0 = max(-32767, min(32767, q0)); q1 = max(-32767, min(32767, q1));
            q2 = max(-32767, min(32767, q2)); q3 = max(-32767, min(32767, q3));
            p0[nt*4] = ((uint32_t)q0 & 0xffffu) | ((uint32_t)q1 << 16);
            p1[nt*4] = ((uint32_t)q2 & 0xffffu) | ((uint32_t)q3 << 16);
        }
    }
}

// ---------------- gather: out[d] = tanh(dinv[d]*(h'[d] + sum h'[s]) + b) ----------------
// h' rows are int16 + per-row scale: half the L2 traffic of fp32.
#define ACCROW(sidx, A) { \
    int2 p_ = *reinterpret_cast<const int2*>(qb + (size_t)(sidx)*128 + lane*4); \
    float rsc_ = rs[sidx]; \
    A.x = fmaf((float)((short)(p_.x)),        rsc_, A.x); \
    A.y = fmaf((float)((short)(p_.x >> 16)),  rsc_, A.y); \
    A.z = fmaf((float)((short)(p_.y)),        rsc_, A.z); \
    A.w = fmaf((float)((short)(p_.y >> 16)),  rsc_, A.w); }

__global__ void __launch_bounds__(256) k_gather(const float* __restrict__ bias){
    int warp = threadIdx.x >> 5, lane = threadIdx.x & 31;
    int g = blockIdx.x*8 + warp;      // grid exact: 20000*8 = 160000
    int t = g / NN, d = g - t*NN;
    const int16_t* qb = g_bufQ + (size_t)t*NN*128;
    const float* rs = g_rscale + t*NN;
    int f4 = lane*4;

    float4 acc  = make_float4(0.f,0.f,0.f,0.f);
    float4 acc2 = make_float4(0.f,0.f,0.f,0.f);
    ACCROW(d, acc);                    // self loop
    int beg = g_rowstart[t*(NN+1)+d], end = g_rowstart[t*(NN+1)+d+1];
    const int* ss = g_sorted + t*EE;
    for (int j = beg; j < end; j += 32){
        int idx = j + lane;
        int sv = (idx < end) ? ss[idx] : 0;
        int cnt = min(32, end - j);
        int kk = 0;
        for (; kk + 2 <= cnt; kk += 2){
            int s0 = __shfl_sync(0xffffffffu, sv, kk);
            int s1 = __shfl_sync(0xffffffffu, sv, kk+1);
            ACCROW(s0, acc);
            ACCROW(s1, acc2);
        }
        if (kk < cnt){
            int s0 = __shfl_sync(0xffffffffu, sv, kk);
            ACCROW(s0, acc);
        }
    }
    float sc = g_dinv[g];
    float4 bb = ld4(bias + f4);
    float4 r;
    r.x = fast_tanh(fmaf(sc, acc.x + acc2.x, bb.x));
    r.y = fast_tanh(fmaf(sc, acc.y + acc2.y, bb.y));
    r.z = fast_tanh(fmaf(sc, acc.z + acc2.z, bb.z));
    r.w = fast_tanh(fmaf(sc, acc.w + acc2.w, bb.w));
    *reinterpret_cast<float4*>(g_bufY + (size_t)g*128 + f4) = r;
}

// ---------------- z = sum over nodes (deterministic two-stage) ----------------
__global__ void __launch_bounds__(128) k_zpart(){
    int t = blockIdx.y, p = blockIdx.x, j = threadIdx.x;
    const float* base = g_bufY + ((size_t)t*NN + p*625)*128 + j;
    float s0=0.f, s1=0.f, s2=0.f, s3=0.f;
    int n = 0;
    for (; n + 4 <= 624; n += 4){
        s0 += base[(size_t)(n+0)*128];
        s1 += base[(size_t)(n+1)*128];
        s2 += base[(size_t)(n+2)*128];
        s3 += base[(size_t)(n+3)*128];
    }
    for (; n < 625; n++) s0 += base[(size_t)n*128];
    g_partial[(t*8+p)*128 + j] = (s0+s1) + (s2+s3);
}

// ---------------- tail: qkv ----------------
__global__ void __launch_bounds__(128) k_qkv(const float* __restrict__ Wq, const float* __restrict__ bq,
                                             const float* __restrict__ Wk, const float* __restrict__ bk,
                                             const float* __restrict__ Wv, const float* __restrict__ bv){
    __shared__ float zs[128];
    int t = blockIdx.x, j = threadIdx.x;
    float zsum = 0.f;
    #pragma unroll
    for (int p = 0; p < 8; p++) zsum += g_partial[(t*8+p)*128 + j];
    zs[j] = zsum; __syncthreads();
    float q = bq[j], k = bk[j], v = bv[j];
    #pragma unroll 4
    for (int i = 0; i < 128; i++){
        float zi = zs[i];
        q = fmaf(zi, Wq[i*128+j], q);
        k = fmaf(zi, Wk[i*128+j], k);
        v = fmaf(zi, Wv[i*128+j], v);
    }
    g_q[t*128+j] = q; g_k[t*128+j] = k; g_v[t*128+j] = v;
}

// ---------------- tail: attention + out proj + MLP + residual + LN + ReLU (fused) ----------------
__global__ void __launch_bounds__(256) k_tail3(const float* __restrict__ Wo, const float* __restrict__ bo,
                                               const float* __restrict__ Wm1, const float* __restrict__ bm1,
                                               const float* __restrict__ Wm2, const float* __restrict__ bm2,
                                               const float* __restrict__ g2, const float* __restrict__ beta2){
    __shared__ float ksh[32*128];
    __shared__ float vsh[32*128];
    __shared__ float qsh[128];
    __shared__ float osh[128];
    __shared__ float ash[8*32];
    __shared__ float xat[128];
    __shared__ float hid[HD2];
    __shared__ float red[128];
    __shared__ float pp[256];
    int t = blockIdx.x, tid = threadIdx.x;

    // --- attention ---
    for (int i = tid; i < 4096; i += 256){ ksh[i] = g_k[i]; vsh[i] = g_v[i]; }
    if (tid < 128) qsh[tid] = g_q[t*128+tid];
    __syncthreads();
    int h = tid >> 5, lane = tid & 31;
    float sc = 0.f;
    const float* qp = qsh + h*16;
    const float* kp = ksh + lane*128 + h*16;
    #pragma unroll
    for (int dd = 0; dd < 16; dd++) sc += qp[dd]*kp[dd];
    sc *= 0.25f;   // 1/sqrt(16)
    float m = sc;
    #pragma unroll
    for (int off = 16; off > 0; off >>= 1) m = fmaxf(m, __shfl_xor_sync(0xffffffffu, m, off));
    float e = __expf(sc - m);
    float sm = e;
    #pragma unroll
    for (int off = 16; off > 0; off >>= 1) sm += __shfl_xor_sync(0xffffffffu, sm, off);
    ash[h*32+lane] = e / sm;
    __syncwarp();
    if (lane < 16){
        float o = 0.f;
        #pragma unroll 4
        for (int s = 0; s < 32; s++) o += ash[h*32+s] * vsh[s*128 + h*16 + lane];
        osh[h*16+lane] = o;
    }
    __syncthreads();
    if (tid < 128){
        float xa = bo[tid];
        #pragma unroll 4
        for (int i = 0; i < 128; i++) xa = fmaf(osh[i], Wo[i*128+tid], xa);
        xat[tid] = xa;
    }
    __syncthreads();

    // --- MLP layer 1 (relu) ---
    for (int mm = tid; mm < HD2; mm += 256){
        float hh = bm1[mm];
        #pragma unroll 4
        for (int j = 0; j < 128; j++) hh = fmaf(xat[j], Wm1[j*HD2+mm], hh);
        hid[mm] = fmaxf(hh, 0.f);
    }
    __syncthreads();

    // --- MLP layer 2 (split over 2 thread-halves) + residual + LN + ReLU ---
    int j = tid & 127, hf = tid >> 7;
    float part = 0.f;
    #pragma unroll 4
    for (int mm = hf*256; mm < hf*256 + 256; mm++) part = fmaf(hid[mm], Wm2[mm*128+j], part);
    pp[tid] = part; __syncthreads();
    float y = 0.f;
    if (tid < 128){ y = pp[tid] + pp[tid+128] + bm2[tid] + xat[tid]; red[tid] = y; }
    __syncthreads();
    #pragma unroll
    for (int off = 64; off > 0; off >>= 1){ if (tid < off) red[tid] += red[tid+off]; __syncthreads(); }
    float mu = red[0] * (1.f/128.f);
    __syncthreads();
    float dv = y - mu;
    if (tid < 128) red[tid] = dv*dv;
    __syncthreads();
    #pragma unroll
    for (int off = 64; off > 0; off >>= 1){ if (tid < off) red[tid] += red[tid+off]; __syncthreads(); }
    float var = red[0] * (1.f/128.f);
    if (tid < 128){
        float yn = dv * rsqrtf(var + 1e-5f) * g2[tid] + beta2[tid];
        g_yr[t*128+tid] = fmaxf(yn, 0.f);
    }
}

// ---------------- tail: pool over T + final linear ----------------
__global__ void __launch_bounds__(128) k_final(const float* __restrict__ Wl, const float* __restrict__ bl,
                                               float* __restrict__ out){
    __shared__ float ps[128];
    int j = threadIdx.x;
    float s = 0.f;
    #pragma unroll
    for (int t = 0; t < TT; t++) s += g_yr[t*128+j];
    ps[j] = s; __syncthreads();
    if (j < CC){
        float o = bl[j];
        #pragma unroll 4
        for (int f = 0; f < 128; f++) o = fmaf(ps[f], Wl[f*CC+j], o);
        out[j] = o;
    }
}

// ---------------- launch ----------------
extern "C" void kernel_launch(void* const* d_in, const int* in_sizes, int n_in,
                              void* d_out, int out_size) {
    const float* x   = (const float*)d_in[0];
    const int*   ei  = (const int*)  d_in[1];
    const float* W0  = (const float*)d_in[2];  const float* b0 = (const float*)d_in[3];
    const float* W1  = (const float*)d_in[4];  const float* b1 = (const float*)d_in[5];
    const float* W2  = (const float*)d_in[6];  const float* b2 = (const float*)d_in[7];
    const float* Wq  = (const float*)d_in[8];  const float* bq = (const float*)d_in[9];
    const float* Wk  = (const float*)d_in[10]; const float* bk = (const float*)d_in[11];
    const float* Wv  = (const float*)d_in[12]; const float* bv = (const float*)d_in[13];
    const float* Wo  = (const float*)d_in[14]; const float* bo = (const float*)d_in[15];
    const float* g2  = (const float*)d_in[16]; const float* be2= (const float*)d_in[17];
    const float* Wm1 = (const float*)d_in[18]; const float* bm1= (const float*)d_in[19];
    const float* Wm2 = (const float*)d_in[20]; const float* bm2= (const float*)d_in[21];
    const float* Wl  = (const float*)d_in[22]; const float* bl = (const float*)d_in[23];
    float* out = (float*)d_out;

    const float* Ws_[3] = {W0, W1, W2};
    const float* bs_[3] = {b0, b1, b2};

    cudaFuncSetAttribute(k_gemm_mma, cudaFuncAttributeMaxDynamicSharedMemorySize, GEMM_SMEM);

    k_init_deg<<<(NT+255)/256, 256>>>();
    k_count<<<(TT*EE)/256, 256>>>(ei);
    k_scan<<<TT, 256>>>();
    k_sort<<<(TT*EE)/256, 256>>>(ei);

    for (int layer = 0; layer < 3; layer++){
        k_gemm_mma<<<NT/128, 256, GEMM_SMEM>>>(x, Ws_[layer], layer);
        k_gather<<<NT/8, 256>>>(bs_[layer]);
    }

    k_zpart<<<dim3(8, TT), 128>>>();
    k_qkv<<<TT, 128>>>(Wq, bq, Wk, bk, Wv, bv);
    k_tail3<<<TT, 256>>>(Wo, bo, Wm1, bm1, Wm2, bm2, g2, be2);
    k_final<<<1, 128>>>(Wl, bl, out);
}

// round 5
// speedup vs baseline: 1.0422x; 1.0422x over previous
#include <cuda_runtime.h>
#include <cuda_bf16.h>
#include <cstdint>

// Problem constants
#define TT   32
#define NN   5000
#define EE   80000
#define HH   128
#define HD2  512
#define CC   10
#define NT   (TT*NN)          // 160000 total nodes

// ---------------- device scratch (static; no allocation) ----------------
__device__ int   g_deg[NT];
__device__ float g_dinv[NT];
__device__ int   g_rowstart[TT*(NN+1)];
__device__ int   g_cursor[NT];
__device__ int   g_sorted[TT*EE];
__device__ float g_bufH[(size_t)NT*HH];   // h' = dinv * (x @ W)
__device__ float g_bufY[(size_t)NT*HH];   // layer output
__device__ __nv_bfloat16 g_Wh[3*16384];   // per-layer W hi
__device__ __nv_bfloat16 g_Wl[3*16384];   // per-layer W lo
__device__ float g_partial[TT*8*HH];
__device__ float g_q[TT*HH], g_k[TT*HH], g_v[TT*HH];
__device__ float g_yr[TT*HH];

__device__ __forceinline__ float4 ld4(const float* p){ return *reinterpret_cast<const float4*>(p); }
__device__ __forceinline__ float fast_tanh(float x){ asm("tanh.approx.f32 %0, %0;" : "+f"(x)); return x; }
__device__ __forceinline__ uint32_t smem_u32(const void* p){
    uint32_t a;
    asm("{ .reg .u64 t; cvta.to.shared.u64 t, %1; cvt.u32.u64 %0, t; }" : "=r"(a) : "l"(p));
    return a;
}
__device__ __forceinline__ uint32_t pack2(__nv_bfloat16 a, __nv_bfloat16 b){
    __nv_bfloat162 t = __halves2bfloat162(a, b);
    return *reinterpret_cast<uint32_t*>(&t);
}

#define LDSM_X4(r0,r1,r2,r3, addr) \
    asm volatile("ldmatrix.sync.aligned.m8n8.x4.shared.b16 {%0,%1,%2,%3}, [%4];" \
        : "=r"(r0),"=r"(r1),"=r"(r2),"=r"(r3) : "r"(addr))
#define LDSM_X4_T(r0,r1,r2,r3, addr) \
    asm volatile("ldmatrix.sync.aligned.m8n8.x4.trans.shared.b16 {%0,%1,%2,%3}, [%4];" \
        : "=r"(r0),"=r"(r1),"=r"(r2),"=r"(r3) : "r"(addr))
#define MMA16816(d, a, b) \
    asm volatile("mma.sync.aligned.m16n8k16.row.col.f32.bf16.bf16.f32 " \
        "{%0,%1,%2,%3}, {%4,%5,%6,%7}, {%8,%9}, {%0,%1,%2,%3};" \
        : "+f"((d)[0]),"+f"((d)[1]),"+f"((d)[2]),"+f"((d)[3]) \
        : "r"((a)[0]),"r"((a)[1]),"r"((a)[2]),"r"((a)[3]), "r"((b)[0]),"r"((b)[1]))

// ---------------- setup kernels ----------------
// count degrees; spare threads also precompute W hi/lo for all 3 layers
__global__ void k_count(const int* __restrict__ ei, const float* __restrict__ W0,
                        const float* __restrict__ W1, const float* __restrict__ W2){
    int i = blockIdx.x*256 + threadIdx.x;      // exact grid TT*EE
    int t = i / EE, e = i - t*EE;
    int dst = ei[t*2*EE + EE + e];
    atomicAdd(&g_deg[t*NN + dst], 1);
    if (i < 3*16384){
        int l = i >> 14, j = i & 16383;
        const float* Wp = (l == 0) ? W0 : ((l == 1) ? W1 : W2);
        float w = Wp[j];
        __nv_bfloat16 h = __float2bfloat16(w);
        g_Wh[i] = h;
        g_Wl[i] = __float2bfloat16(w - __bfloat162float(h));
    }
}

// prefix-sum degrees into CSR rowstarts; zero g_deg for next graph replay
__global__ void __launch_bounds__(256) k_scan(){
    int t = blockIdx.x, tid = threadIdx.x;
    __shared__ int sh[256];
    __shared__ int sbase;
    if (tid == 0) sbase = 0;
    __syncthreads();
    for (int c = 0; c < 20; c++){
        int idx = c*256 + tid;
        int cnt = 0;
        if (idx < NN){
            cnt = g_deg[t*NN+idx];
            g_deg[t*NN+idx] = 0;       // reset for next replay
        }
        sh[tid] = cnt; __syncthreads();
        #pragma unroll
        for (int off = 1; off < 256; off <<= 1){
            int v = (tid >= off) ? sh[tid-off] : 0;
            __syncthreads();
            sh[tid] += v;
            __syncthreads();
        }
        int incl = sh[tid];
        int base = sbase;
        if (idx < NN){
            int ex = base + incl - cnt;
            g_rowstart[t*(NN+1)+idx] = ex;
            g_cursor[t*NN+idx] = ex;
            g_dinv[t*NN+idx] = rsqrtf((float)(cnt + 1));
        }
        __syncthreads();
        if (tid == 255) sbase = base + incl;
        __syncthreads();
    }
    if (tid == 0) g_rowstart[t*(NN+1)+NN] = sbase;  // == EE
}

__global__ void k_sort(const int* __restrict__ ei){
    int i = blockIdx.x*256 + threadIdx.x;
    int t = i / EE, e = i - t*EE;
    int src = ei[t*2*EE + e];
    int dst = ei[t*2*EE + EE + e];
    int pos = atomicAdd(&g_cursor[t*NN + dst], 1);
    g_sorted[t*EE + pos] = src;
}

// ---------------- tensor-core GEMM: h' = dinv * (X @ W) ----------------
// mma.sync m16n8k16 bf16, hi/lo split: D = Ah*Bh + Al*Bh + Ah*Bl.
// CTA: 128x128; 8 warps, each 32 rows x 64 cols; K=128 in 8 steps.
#define PADW 136
#define GEMM_SMEM (4*128*PADW*2)

__global__ void __launch_bounds__(256) k_gemm_mma(const float* __restrict__ X0,
                                                  int layer){
    extern __shared__ __align__(16) char sm_[];
    __nv_bfloat16* Ah = (__nv_bfloat16*)sm_;
    __nv_bfloat16* Al = Ah + 128*PADW;
    __nv_bfloat16* Bh = Al + 128*PADW;
    __nv_bfloat16* Bl = Bh + 128*PADW;
    const float* __restrict__ X = (layer == 0) ? X0 : g_bufY;
    const int tid = threadIdx.x, wid = tid >> 5, lane = tid & 31;
    const int bm = blockIdx.x * 128;

    // ---- fill B from precomputed bf16 hi/lo (pure copy, 16B stores) ----
    {
        const uint4* wh = reinterpret_cast<const uint4*>(g_Wh + layer*16384);
        const uint4* wl = reinterpret_cast<const uint4*>(g_Wl + layer*16384);
        #pragma unroll
        for (int i = 0; i < 8; i++){
            int u   = tid + i*256;            // 0..2047 (each = 8 bf16)
            int row = u >> 4;                 // 0..127
            int c0  = (u & 15) << 3;          // 0..120
            int s = row*PADW + c0;
            *reinterpret_cast<uint4*>(Bh + s) = wh[u];
            *reinterpret_cast<uint4*>(Bl + s) = wl[u];
        }
    }
    // ---- fill A (X rows) as hi/lo bf16 ----
    #pragma unroll
    for (int i = 0; i < 16; i++){
        int idx4 = tid + i*256;              // 0..4095
        int row  = idx4 >> 5;                // 0..127
        int c0   = (idx4 & 31) << 2;         // 0..124
        float4 v = ld4(X + (size_t)(bm + row)*128 + c0);
        __nv_bfloat16 ah0 = __float2bfloat16(v.x), ah1 = __float2bfloat16(v.y);
        __nv_bfloat16 ah2 = __float2bfloat16(v.z), ah3 = __float2bfloat16(v.w);
        uint2 avh, avl;
        avh.x = pack2(ah0, ah1); avh.y = pack2(ah2, ah3);
        avl.x = pack2(__float2bfloat16(v.x - __bfloat162float(ah0)),
                      __float2bfloat16(v.y - __bfloat162float(ah1)));
        avl.y = pack2(__float2bfloat16(v.z - __bfloat162float(ah2)),
                      __float2bfloat16(v.w - __bfloat162float(ah3)));
        int s = row*PADW + c0;
        *reinterpret_cast<uint2*>(Ah + s) = avh;
        *reinterpret_cast<uint2*>(Al + s) = avl;
    }
    __syncthreads();

    const int wr = (wid & 3) * 32;           // warp row base
    const int wc = (wid >> 2) * 64;          // warp col base
    const int lhalf = (lane >> 4) << 3;

    const uint32_t aBaseH = smem_u32(Ah) + (uint32_t)(((wr + (lane & 15))*PADW + lhalf) * 2);
    const uint32_t aBaseL = aBaseH + (uint32_t)(128*PADW*2);
    const uint32_t bBaseH = smem_u32(Bh) + (uint32_t)(((lane & 15)*PADW + wc + lhalf) * 2);
    const uint32_t bBaseL = bBaseH + (uint32_t)(128*PADW*2);

    float acc[2][8][4];
    #pragma unroll
    for (int mt = 0; mt < 2; mt++)
        #pragma unroll
        for (int nt = 0; nt < 8; nt++)
            #pragma unroll
            for (int c = 0; c < 4; c++) acc[mt][nt][c] = 0.f;

    #pragma unroll
    for (int ks = 0; ks < 8; ks++){
        const uint32_t k0b  = (uint32_t)(ks*16*2);
        const uint32_t k0rb = (uint32_t)(ks*16*PADW*2);
        uint32_t ah[2][4], al[2][4], bh[8][2], bl[8][2];
        #pragma unroll
        for (int mt = 0; mt < 2; mt++){
            uint32_t aH = aBaseH + (uint32_t)(mt*16*PADW*2) + k0b;
            uint32_t aL = aBaseL + (uint32_t)(mt*16*PADW*2) + k0b;
            LDSM_X4(ah[mt][0], ah[mt][1], ah[mt][2], ah[mt][3], aH);
            LDSM_X4(al[mt][0], al[mt][1], al[mt][2], al[mt][3], aL);
        }
        #pragma unroll
        for (int p = 0; p < 4; p++){
            uint32_t bH = bBaseH + k0rb + (uint32_t)(p*16*2);
            uint32_t bL = bBaseL + k0rb + (uint32_t)(p*16*2);
            LDSM_X4_T(bh[2*p][0], bh[2*p][1], bh[2*p+1][0], bh[2*p+1][1], bH);
            LDSM_X4_T(bl[2*p][0], bl[2*p][1], bl[2*p+1][0], bl[2*p+1][1], bL);
        }
        #pragma unroll
        for (int mt = 0; mt < 2; mt++)
            #pragma unroll
            for (int nt = 0; nt < 8; nt++){
                MMA16816(acc[mt][nt], ah[mt], bh[nt]);
                MMA16816(acc[mt][nt], al[mt], bh[nt]);
                MMA16816(acc[mt][nt], ah[mt], bl[nt]);
            }
    }

    // ---- epilogue: scale by dinv[row], store fp32 ----
    const int lr = lane >> 2, lq = lane & 3;
    #pragma unroll
    for (int mt = 0; mt < 2; mt++){
        int r0 = bm + wr + mt*16 + lr;
        float s0 = g_dinv[r0], s1 = g_dinv[r0 + 8];
        float* p0 = g_bufH + (size_t)r0*128 + wc + lq*2;
        float* p1 = p0 + (size_t)8*128;
        #pragma unroll
        for (int nt = 0; nt < 8; nt++){
            float2 v0 = make_float2(acc[mt][nt][0]*s0, acc[mt][nt][1]*s0);
            float2 v1 = make_float2(acc[mt][nt][2]*s1, acc[mt][nt][3]*s1);
            *reinterpret_cast<float2*>(p0 + nt*8) = v0;
            *reinterpret_cast<float2*>(p1 + nt*8) = v1;
        }
    }
}

// ---------------- gather: out[d] = tanh(dinv[d]*(h'[d] + sum h'[s]) + b) ----------------
// 4-way unrolled independent row loads for latency hiding.
#define ADD4(A, V) { A.x += V.x; A.y += V.y; A.z += V.z; A.w += V.w; }

__global__ void __launch_bounds__(256) k_gather(const float* __restrict__ bias){
    int warp = threadIdx.x >> 5, lane = threadIdx.x & 31;
    int g = blockIdx.x*8 + warp;      // grid exact: 20000*8 = 160000
    int t = g / NN, d = g - t*NN;
    const float* hb = g_bufH + (size_t)t*NN*128;
    int f4 = lane*4;

    float4 a0 = ld4(hb + (size_t)d*128 + f4);   // self loop
    float4 a1 = make_float4(0.f,0.f,0.f,0.f);
    float4 a2 = make_float4(0.f,0.f,0.f,0.f);
    float4 a3 = make_float4(0.f,0.f,0.f,0.f);
    int beg = g_rowstart[t*(NN+1)+d], end = g_rowstart[t*(NN+1)+d+1];
    const int* ss = g_sorted + t*EE;
    for (int j = beg; j < end; j += 32){
        int idx = j + lane;
        int sv = (idx < end) ? ss[idx] : 0;
        int cnt = min(32, end - j);
        int kk = 0;
        for (; kk + 4 <= cnt; kk += 4){
            int s0 = __shfl_sync(0xffffffffu, sv, kk);
            int s1 = __shfl_sync(0xffffffffu, sv, kk+1);
            int s2 = __shfl_sync(0xffffffffu, sv, kk+2);
            int s3 = __shfl_sync(0xffffffffu, sv, kk+3);
            float4 v0 = ld4(hb + (size_t)s0*128 + f4);
            float4 v1 = ld4(hb + (size_t)s1*128 + f4);
            float4 v2 = ld4(hb + (size_t)s2*128 + f4);
            float4 v3 = ld4(hb + (size_t)s3*128 + f4);
            ADD4(a0, v0); ADD4(a1, v1); ADD4(a2, v2); ADD4(a3, v3);
        }
        for (; kk < cnt; kk++){
            int s0 = __shfl_sync(0xffffffffu, sv, kk);
            float4 v0 = ld4(hb + (size_t)s0*128 + f4);
            ADD4(a0, v0);
        }
    }
    float sc = g_dinv[g];
    float4 bb = ld4(bias + f4);
    float4 r;
    r.x = fast_tanh(fmaf(sc, (a0.x + a1.x) + (a2.x + a3.x), bb.x));
    r.y = fast_tanh(fmaf(sc, (a0.y + a1.y) + (a2.y + a3.y), bb.y));
    r.z = fast_tanh(fmaf(sc, (a0.z + a1.z) + (a2.z + a3.z), bb.z));
    r.w = fast_tanh(fmaf(sc, (a0.w + a1.w) + (a2.w + a3.w), bb.w));
    *reinterpret_cast<float4*>(g_bufY + (size_t)g*128 + f4) = r;
}

// ---------------- z = sum over nodes (deterministic two-stage) ----------------
__global__ void __launch_bounds__(128) k_zpart(){
    int t = blockIdx.y, p = blockIdx.x, j = threadIdx.x;
    const float* base = g_bufY + ((size_t)t*NN + p*625)*128 + j;
    float s0=0.f, s1=0.f, s2=0.f, s3=0.f;
    int n = 0;
    for (; n + 4 <= 624; n += 4){
        s0 += base[(size_t)(n+0)*128];
        s1 += base[(size_t)(n+1)*128];
        s2 += base[(size_t)(n+2)*128];
        s3 += base[(size_t)(n+3)*128];
    }
    for (; n < 625; n++) s0 += base[(size_t)n*128];
    g_partial[(t*8+p)*128 + j] = (s0+s1) + (s2+s3);
}

// ---------------- tail: qkv ----------------
__global__ void __launch_bounds__(128) k_qkv(const float* __restrict__ Wq, const float* __restrict__ bq,
                                             const float* __restrict__ Wk, const float* __restrict__ bk,
                                             const float* __restrict__ Wv, const float* __restrict__ bv){
    __shared__ float zs[128];
    int t = blockIdx.x, j = threadIdx.x;
    float zsum = 0.f;
    #pragma unroll
    for (int p = 0; p < 8; p++) zsum += g_partial[(t*8+p)*128 + j];
    zs[j] = zsum; __syncthreads();
    float q = bq[j], k = bk[j], v = bv[j];
    #pragma unroll 4
    for (int i = 0; i < 128; i++){
        float zi = zs[i];
        q = fmaf(zi, Wq[i*128+j], q);
        k = fmaf(zi, Wk[i*128+j], k);
        v = fmaf(zi, Wv[i*128+j], v);
    }
    g_q[t*128+j] = q; g_k[t*128+j] = k; g_v[t*128+j] = v;
}

// ---------------- tail: attention + out proj + MLP + residual + LN + ReLU (fused) ----------------
__global__ void __launch_bounds__(256) k_tail3(const float* __restrict__ Wo, const float* __restrict__ bo,
                                               const float* __restrict__ Wm1, const float* __restrict__ bm1,
                                               const float* __restrict__ Wm2, const float* __restrict__ bm2,
                                               const float* __restrict__ g2, const float* __restrict__ beta2){
    __shared__ float ksh[32*128];
    __shared__ float vsh[32*128];
    __shared__ float qsh[128];
    __shared__ float osh[128];
    __shared__ float ash[8*32];
    __shared__ float xat[128];
    __shared__ float hid[HD2];
    __shared__ float red[128];
    __shared__ float pp[256];
    int t = blockIdx.x, tid = threadIdx.x;

    // --- attention ---
    for (int i = tid; i < 4096; i += 256){ ksh[i] = g_k[i]; vsh[i] = g_v[i]; }
    if (tid < 128) qsh[tid] = g_q[t*128+tid];
    __syncthreads();
    int h = tid >> 5, lane = tid & 31;
    float sc = 0.f;
    const float* qp = qsh + h*16;
    const float* kp = ksh + lane*128 + h*16;
    #pragma unroll
    for (int dd = 0; dd < 16; dd++) sc += qp[dd]*kp[dd];
    sc *= 0.25f;   // 1/sqrt(16)
    float m = sc;
    #pragma unroll
    for (int off = 16; off > 0; off >>= 1) m = fmaxf(m, __shfl_xor_sync(0xffffffffu, m, off));
    float e = __expf(sc - m);
    float sm = e;
    #pragma unroll
    for (int off = 16; off > 0; off >>= 1) sm += __shfl_xor_sync(0xffffffffu, sm, off);
    ash[h*32+lane] = e / sm;
    __syncwarp();
    if (lane < 16){
        float o = 0.f;
        #pragma unroll 4
        for (int s = 0; s < 32; s++) o += ash[h*32+s] * vsh[s*128 + h*16 + lane];
        osh[h*16+lane] = o;
    }
    __syncthreads();
    if (tid < 128){
        float xa = bo[tid];
        #pragma unroll 4
        for (int i = 0; i < 128; i++) xa = fmaf(osh[i], Wo[i*128+tid], xa);
        xat[tid] = xa;
    }
    __syncthreads();

    // --- MLP layer 1 (relu) ---
    for (int mm = tid; mm < HD2; mm += 256){
        float hh = bm1[mm];
        #pragma unroll 4
        for (int j = 0; j < 128; j++) hh = fmaf(xat[j], Wm1[j*HD2+mm], hh);
        hid[mm] = fmaxf(hh, 0.f);
    }
    __syncthreads();

    // --- MLP layer 2 (split over 2 thread-halves) + residual + LN + ReLU ---
    int j = tid & 127, hf = tid >> 7;
    float part = 0.f;
    #pragma unroll 4
    for (int mm = hf*256; mm < hf*256 + 256; mm++) part = fmaf(hid[mm], Wm2[mm*128+j], part);
    pp[tid] = part; __syncthreads();
    float y = 0.f;
    if (tid < 128){ y = pp[tid] + pp[tid+128] + bm2[tid] + xat[tid]; red[tid] = y; }
    __syncthreads();
    #pragma unroll
    for (int off = 64; off > 0; off >>= 1){ if (tid < off) red[tid] += red[tid+off]; __syncthreads(); }
    float mu = red[0] * (1.f/128.f);
    __syncthreads();
    float dv = y - mu;
    if (tid < 128) red[tid] = dv*dv;
    __syncthreads();
    #pragma unroll
    for (int off = 64; off > 0; off >>= 1){ if (tid < off) red[tid] += red[tid+off]; __syncthreads(); }
    float var = red[0] * (1.f/128.f);
    if (tid < 128){
        float yn = dv * rsqrtf(var + 1e-5f) * g2[tid] + beta2[tid];
        g_yr[t*128+tid] = fmaxf(yn, 0.f);
    }
}

// ---------------- tail: pool over T + final linear ----------------
__global__ void __launch_bounds__(128) k_final(const float* __restrict__ Wl, const float* __restrict__ bl,
                                               float* __restrict__ out){
    __shared__ float ps[128];
    int j = threadIdx.x;
    float s = 0.f;
    #pragma unroll
    for (int t = 0; t < TT; t++) s += g_yr[t*128+j];
    ps[j] = s; __syncthreads();
    if (j < CC){
        float o = bl[j];
        #pragma unroll 4
        for (int f = 0; f < 128; f++) o = fmaf(ps[f], Wl[f*CC+j], o);
        out[j] = o;
    }
}

// ---------------- launch ----------------
extern "C" void kernel_launch(void* const* d_in, const int* in_sizes, int n_in,
                              void* d_out, int out_size) {
    const float* x   = (const float*)d_in[0];
    const int*   ei  = (const int*)  d_in[1];
    const float* W0  = (const float*)d_in[2];  const float* b0 = (const float*)d_in[3];
    const float* W1  = (const float*)d_in[4];  const float* b1 = (const float*)d_in[5];
    const float* W2  = (const float*)d_in[6];  const float* b2 = (const float*)d_in[7];
    const float* Wq  = (const float*)d_in[8];  const float* bq = (const float*)d_in[9];
    const float* Wk  = (const float*)d_in[10]; const float* bk = (const float*)d_in[11];
    const float* Wv  = (const float*)d_in[12]; const float* bv = (const float*)d_in[13];
    const float* Wo  = (const float*)d_in[14]; const float* bo = (const float*)d_in[15];
    const float* g2  = (const float*)d_in[16]; const float* be2= (const float*)d_in[17];
    const float* Wm1 = (const float*)d_in[18]; const float* bm1= (const float*)d_in[19];
    const float* Wm2 = (const float*)d_in[20]; const float* bm2= (const float*)d_in[21];
    const float* Wl  = (const float*)d_in[22]; const float* bl = (const float*)d_in[23];
    float* out = (float*)d_out;

    const float* bs_[3] = {b0, b1, b2};

    cudaFuncSetAttribute(k_gemm_mma, cudaFuncAttributeMaxDynamicSharedMemorySize, GEMM_SMEM);

    k_count<<<(TT*EE)/256, 256>>>(ei, W0, W1, W2);
    k_scan<<<TT, 256>>>();
    k_sort<<<(TT*EE)/256, 256>>>(ei);

    for (int layer = 0; layer < 3; layer++){
        k_gemm_mma<<<NT/128, 256, GEMM_SMEM>>>(x, layer);
        k_gather<<<NT/8, 256>>>(bs_[layer]);
    }

    k_zpart<<<dim3(8, TT), 128>>>();
    k_qkv<<<TT, 128>>>(Wq, bq, Wk, bk, Wv, bv);
    k_tail3<<<TT, 256>>>(Wo, bo, Wm1, bm1, Wm2, bm2, g2, be2);
    k_final<<<1, 128>>>(Wl, bl, out);
}

// round 6
// speedup vs baseline: 1.0624x; 1.0194x over previous
#include <cuda_runtime.h>
#include <cuda_bf16.h>
#include <cstdint>

// Problem constants
#define TT   32
#define NN   5000
#define EE   80000
#define HH   128
#define HD2  512
#define CC   10
#define NT   (TT*NN)          // 160000 total nodes

// ---------------- device scratch (static; no allocation) ----------------
__device__ int   g_deg[NT];
__device__ float g_dinv[NT];
__device__ int   g_rowstart[TT*(NN+1)];
__device__ int   g_cursor[NT];
__device__ int   g_sorted[TT*EE];
__device__ float g_bufH[(size_t)NT*HH];   // h' = dinv * (x @ W)
__device__ float g_bufY[(size_t)NT*HH];   // layer output
__device__ __nv_bfloat16 g_Wh[3*16384];   // per-layer W hi
__device__ __nv_bfloat16 g_Wl[3*16384];   // per-layer W lo
__device__ float g_partial[TT*8*HH];
__device__ float g_q[TT*HH], g_k[TT*HH], g_v[TT*HH];
__device__ float g_yr[TT*HH];

__device__ __forceinline__ float4 ld4(const float* p){ return *reinterpret_cast<const float4*>(p); }
__device__ __forceinline__ float fast_tanh(float x){ asm("tanh.approx.f32 %0, %0;" : "+f"(x)); return x; }
__device__ __forceinline__ uint32_t smem_u32(const void* p){
    uint32_t a;
    asm("{ .reg .u64 t; cvta.to.shared.u64 t, %1; cvt.u32.u64 %0, t; }" : "=r"(a) : "l"(p));
    return a;
}
__device__ __forceinline__ uint32_t pack2(__nv_bfloat16 a, __nv_bfloat16 b){
    __nv_bfloat162 t = __halves2bfloat162(a, b);
    return *reinterpret_cast<uint32_t*>(&t);
}

#define LDSM_X4(r0,r1,r2,r3, addr) \
    asm volatile("ldmatrix.sync.aligned.m8n8.x4.shared.b16 {%0,%1,%2,%3}, [%4];" \
        : "=r"(r0),"=r"(r1),"=r"(r2),"=r"(r3) : "r"(addr))
#define LDSM_X4_T(r0,r1,r2,r3, addr) \
    asm volatile("ldmatrix.sync.aligned.m8n8.x4.trans.shared.b16 {%0,%1,%2,%3}, [%4];" \
        : "=r"(r0),"=r"(r1),"=r"(r2),"=r"(r3) : "r"(addr))
#define MMA16816(d, a, b) \
    asm volatile("mma.sync.aligned.m16n8k16.row.col.f32.bf16.bf16.f32 " \
        "{%0,%1,%2,%3}, {%4,%5,%6,%7}, {%8,%9}, {%0,%1,%2,%3};" \
        : "+f"((d)[0]),"+f"((d)[1]),"+f"((d)[2]),"+f"((d)[3]) \
        : "r"((a)[0]),"r"((a)[1]),"r"((a)[2]),"r"((a)[3]), "r"((b)[0]),"r"((b)[1]))

// ---------------- setup kernels ----------------
// count degrees; spare threads also precompute W hi/lo for all 3 layers
__global__ void k_count(const int* __restrict__ ei, const float* __restrict__ W0,
                        const float* __restrict__ W1, const float* __restrict__ W2){
    int i = blockIdx.x*256 + threadIdx.x;      // exact grid TT*EE
    int t = i / EE, e = i - t*EE;
    int dst = ei[t*2*EE + EE + e];
    atomicAdd(&g_deg[t*NN + dst], 1);
    if (i < 3*16384){
        int l = i >> 14, j = i & 16383;
        const float* Wp = (l == 0) ? W0 : ((l == 1) ? W1 : W2);
        float w = Wp[j];
        __nv_bfloat16 h = __float2bfloat16(w);
        g_Wh[i] = h;
        g_Wl[i] = __float2bfloat16(w - __bfloat162float(h));
    }
}

// prefix-sum degrees into CSR rowstarts (warp-shuffle scan); zero g_deg for replay
__global__ void __launch_bounds__(256) k_scan(){
    int t = blockIdx.x, tid = threadIdx.x, lane = tid & 31, w = tid >> 5;
    __shared__ int wsum[8];
    __shared__ int sbase;
    if (tid == 0) sbase = 0;
    __syncthreads();
    for (int c = 0; c < 20; c++){
        int idx = c*256 + tid;
        int cnt = 0;
        if (idx < NN){
            cnt = g_deg[t*NN+idx];
            g_deg[t*NN+idx] = 0;       // reset for next replay
        }
        int v = cnt;
        #pragma unroll
        for (int off = 1; off < 32; off <<= 1){
            int u = __shfl_up_sync(0xffffffffu, v, off);
            if (lane >= off) v += u;
        }
        if (lane == 31) wsum[w] = v;
        __syncthreads();
        int woff = 0;
        #pragma unroll
        for (int k = 0; k < 8; k++) woff += (k < w) ? wsum[k] : 0;
        int base = sbase;
        int incl = v + woff;
        if (idx < NN){
            int ex = base + incl - cnt;
            g_rowstart[t*(NN+1)+idx] = ex;
            g_cursor[t*NN+idx] = ex;
            g_dinv[t*NN+idx] = rsqrtf((float)(cnt + 1));
        }
        __syncthreads();
        if (tid == 255) sbase = base + incl;   // total after this chunk
        __syncthreads();
    }
    if (tid == 0) g_rowstart[t*(NN+1)+NN] = sbase;  // == EE
}

__global__ void k_sort(const int* __restrict__ ei){
    int i = blockIdx.x*256 + threadIdx.x;
    int t = i / EE, e = i - t*EE;
    int src = ei[t*2*EE + e];
    int dst = ei[t*2*EE + EE + e];
    int pos = atomicAdd(&g_cursor[t*NN + dst], 1);
    g_sorted[t*EE + pos] = src;
}

// ---------------- tensor-core GEMM: h' = dinv * (X @ W) ----------------
// mma.sync m16n8k16 bf16, hi/lo split: D = Ah*Bh + Al*Bh + Ah*Bl.
// BM=64 tile -> 104.4KB smem -> 2 CTAs/SM (fill of one overlaps MMA of other).
// 8 warps: rows (wid&1)*32, cols (wid>>1)*32; K=128 in 8 steps.
#define PADW 136
#define GEMM_SMEM ((2*64*PADW + 2*128*PADW)*2)

__global__ void __launch_bounds__(256, 2) k_gemm_mma(const float* __restrict__ X0,
                                                     int layer){
    extern __shared__ __align__(16) char sm_[];
    __nv_bfloat16* Ah = (__nv_bfloat16*)sm_;
    __nv_bfloat16* Al = Ah + 64*PADW;
    __nv_bfloat16* Bh = Al + 64*PADW;
    __nv_bfloat16* Bl = Bh + 128*PADW;
    const float* __restrict__ X = (layer == 0) ? X0 : g_bufY;
    const int tid = threadIdx.x, wid = tid >> 5, lane = tid & 31;
    const int bm = blockIdx.x * 64;

    // ---- fill B from precomputed bf16 hi/lo (pure copy, 16B stores) ----
    {
        const uint4* wh = reinterpret_cast<const uint4*>(g_Wh + layer*16384);
        const uint4* wl = reinterpret_cast<const uint4*>(g_Wl + layer*16384);
        #pragma unroll
        for (int i = 0; i < 8; i++){
            int u   = tid + i*256;            // 0..2047 (each = 8 bf16)
            int row = u >> 4;                 // 0..127
            int c0  = (u & 15) << 3;          // 0..120
            int s = row*PADW + c0;
            *reinterpret_cast<uint4*>(Bh + s) = wh[u];
            *reinterpret_cast<uint4*>(Bl + s) = wl[u];
        }
    }
    // ---- fill A (X rows bm..bm+63) as hi/lo bf16 ----
    #pragma unroll
    for (int i = 0; i < 8; i++){
        int idx4 = tid + i*256;              // 0..2047
        int row  = idx4 >> 5;                // 0..63
        int c0   = (idx4 & 31) << 2;         // 0..124
        float4 v = ld4(X + (size_t)(bm + row)*128 + c0);
        __nv_bfloat16 ah0 = __float2bfloat16(v.x), ah1 = __float2bfloat16(v.y);
        __nv_bfloat16 ah2 = __float2bfloat16(v.z), ah3 = __float2bfloat16(v.w);
        uint2 avh, avl;
        avh.x = pack2(ah0, ah1); avh.y = pack2(ah2, ah3);
        avl.x = pack2(__float2bfloat16(v.x - __bfloat162float(ah0)),
                      __float2bfloat16(v.y - __bfloat162float(ah1)));
        avl.y = pack2(__float2bfloat16(v.z - __bfloat162float(ah2)),
                      __float2bfloat16(v.w - __bfloat162float(ah3)));
        int s = row*PADW + c0;
        *reinterpret_cast<uint2*>(Ah + s) = avh;
        *reinterpret_cast<uint2*>(Al + s) = avl;
    }
    __syncthreads();

    const int wr = (wid & 1) * 32;           // warp row base (0/32)
    const int wc = (wid >> 1) * 32;          // warp col base (0..96)
    const int lhalf = (lane >> 4) << 3;

    const uint32_t aBaseH = smem_u32(Ah) + (uint32_t)(((wr + (lane & 15))*PADW + lhalf) * 2);
    const uint32_t aBaseL = aBaseH + (uint32_t)(64*PADW*2);
    const uint32_t bBaseH = smem_u32(Bh) + (uint32_t)(((lane & 15)*PADW + wc + lhalf) * 2);
    const uint32_t bBaseL = bBaseH + (uint32_t)(128*PADW*2);

    float acc[2][4][4];
    #pragma unroll
    for (int mt = 0; mt < 2; mt++)
        #pragma unroll
        for (int nt = 0; nt < 4; nt++)
            #pragma unroll
            for (int c = 0; c < 4; c++) acc[mt][nt][c] = 0.f;

    #pragma unroll
    for (int ks = 0; ks < 8; ks++){
        const uint32_t k0b  = (uint32_t)(ks*16*2);
        const uint32_t k0rb = (uint32_t)(ks*16*PADW*2);
        uint32_t ah[2][4], al[2][4], bh[4][2], bl[4][2];
        #pragma unroll
        for (int mt = 0; mt < 2; mt++){
            uint32_t aH = aBaseH + (uint32_t)(mt*16*PADW*2) + k0b;
            uint32_t aL = aBaseL + (uint32_t)(mt*16*PADW*2) + k0b;
            LDSM_X4(ah[mt][0], ah[mt][1], ah[mt][2], ah[mt][3], aH);
            LDSM_X4(al[mt][0], al[mt][1], al[mt][2], al[mt][3], aL);
        }
        #pragma unroll
        for (int p = 0; p < 2; p++){
            uint32_t bH = bBaseH + k0rb + (uint32_t)(p*16*2);
            uint32_t bL = bBaseL + k0rb + (uint32_t)(p*16*2);
            LDSM_X4_T(bh[2*p][0], bh[2*p][1], bh[2*p+1][0], bh[2*p+1][1], bH);
            LDSM_X4_T(bl[2*p][0], bl[2*p][1], bl[2*p+1][0], bl[2*p+1][1], bL);
        }
        #pragma unroll
        for (int mt = 0; mt < 2; mt++)
            #pragma unroll
            for (int nt = 0; nt < 4; nt++){
                MMA16816(acc[mt][nt], ah[mt], bh[nt]);
                MMA16816(acc[mt][nt], al[mt], bh[nt]);
                MMA16816(acc[mt][nt], ah[mt], bl[nt]);
            }
    }

    // ---- epilogue: scale by dinv[row], store fp32 ----
    const int lr = lane >> 2, lq = lane & 3;
    #pragma unroll
    for (int mt = 0; mt < 2; mt++){
        int r0 = bm + wr + mt*16 + lr;
        float s0 = g_dinv[r0], s1 = g_dinv[r0 + 8];
        float* p0 = g_bufH + (size_t)r0*128 + wc + lq*2;
        float* p1 = p0 + (size_t)8*128;
        #pragma unroll
        for (int nt = 0; nt < 4; nt++){
            float2 v0 = make_float2(acc[mt][nt][0]*s0, acc[mt][nt][1]*s0);
            float2 v1 = make_float2(acc[mt][nt][2]*s1, acc[mt][nt][3]*s1);
            *reinterpret_cast<float2*>(p0 + nt*8) = v0;
            *reinterpret_cast<float2*>(p1 + nt*8) = v1;
        }
    }
}

// ---------------- gather: out[d] = tanh(dinv[d]*(h'[d] + sum h'[s]) + b) ----------------
#define ADD4(A, V) { A.x += V.x; A.y += V.y; A.z += V.z; A.w += V.w; }

__global__ void __launch_bounds__(256) k_gather(const float* __restrict__ bias){
    int warp = threadIdx.x >> 5, lane = threadIdx.x & 31;
    int g = blockIdx.x*8 + warp;      // grid exact: 20000*8 = 160000
    int t = g / NN, d = g - t*NN;
    const float* hb = g_bufH + (size_t)t*NN*128;
    int f4 = lane*4;

    float4 a0 = ld4(hb + (size_t)d*128 + f4);   // self loop
    float4 a1 = make_float4(0.f,0.f,0.f,0.f);
    float4 a2 = make_float4(0.f,0.f,0.f,0.f);
    float4 a3 = make_float4(0.f,0.f,0.f,0.f);
    int beg = g_rowstart[t*(NN+1)+d], end = g_rowstart[t*(NN+1)+d+1];
    const int* ss = g_sorted + t*EE;
    for (int j = beg; j < end; j += 32){
        int idx = j + lane;
        int sv = (idx < end) ? ss[idx] : 0;
        int cnt = min(32, end - j);
        int kk = 0;
        for (; kk + 4 <= cnt; kk += 4){
            int s0 = __shfl_sync(0xffffffffu, sv, kk);
            int s1 = __shfl_sync(0xffffffffu, sv, kk+1);
            int s2 = __shfl_sync(0xffffffffu, sv, kk+2);
            int s3 = __shfl_sync(0xffffffffu, sv, kk+3);
            float4 v0 = ld4(hb + (size_t)s0*128 + f4);
            float4 v1 = ld4(hb + (size_t)s1*128 + f4);
            float4 v2 = ld4(hb + (size_t)s2*128 + f4);
            float4 v3 = ld4(hb + (size_t)s3*128 + f4);
            ADD4(a0, v0); ADD4(a1, v1); ADD4(a2, v2); ADD4(a3, v3);
        }
        for (; kk < cnt; kk++){
            int s0 = __shfl_sync(0xffffffffu, sv, kk);
            float4 v0 = ld4(hb + (size_t)s0*128 + f4);
            ADD4(a0, v0);
        }
    }
    float sc = g_dinv[g];
    float4 bb = ld4(bias + f4);
    float4 r;
    r.x = fast_tanh(fmaf(sc, (a0.x + a1.x) + (a2.x + a3.x), bb.x));
    r.y = fast_tanh(fmaf(sc, (a0.y + a1.y) + (a2.y + a3.y), bb.y));
    r.z = fast_tanh(fmaf(sc, (a0.z + a1.z) + (a2.z + a3.z), bb.z));
    r.w = fast_tanh(fmaf(sc, (a0.w + a1.w) + (a2.w + a3.w), bb.w));
    *reinterpret_cast<float4*>(g_bufY + (size_t)g*128 + f4) = r;
}

// ---------------- z = sum over nodes (deterministic two-stage) ----------------
__global__ void __launch_bounds__(128) k_zpart(){
    int t = blockIdx.y, p = blockIdx.x, j = threadIdx.x;
    const float* base = g_bufY + ((size_t)t*NN + p*625)*128 + j;
    float s0=0.f, s1=0.f, s2=0.f, s3=0.f;
    int n = 0;
    for (; n + 4 <= 624; n += 4){
        s0 += base[(size_t)(n+0)*128];
        s1 += base[(size_t)(n+1)*128];
        s2 += base[(size_t)(n+2)*128];
        s3 += base[(size_t)(n+3)*128];
    }
    for (; n < 625; n++) s0 += base[(size_t)n*128];
    g_partial[(t*8+p)*128 + j] = (s0+s1) + (s2+s3);
}

// ---------------- tail: qkv ----------------
__global__ void __launch_bounds__(128) k_qkv(const float* __restrict__ Wq, const float* __restrict__ bq,
                                             const float* __restrict__ Wk, const float* __restrict__ bk,
                                             const float* __restrict__ Wv, const float* __restrict__ bv){
    __shared__ float zs[128];
    int t = blockIdx.x, j = threadIdx.x;
    float zsum = 0.f;
    #pragma unroll
    for (int p = 0; p < 8; p++) zsum += g_partial[(t*8+p)*128 + j];
    zs[j] = zsum; __syncthreads();
    float q = bq[j], k = bk[j], v = bv[j];
    #pragma unroll 4
    for (int i = 0; i < 128; i++){
        float zi = zs[i];
        q = fmaf(zi, Wq[i*128+j], q);
        k = fmaf(zi, Wk[i*128+j], k);
        v = fmaf(zi, Wv[i*128+j], v);
    }
    g_q[t*128+j] = q; g_k[t*128+j] = k; g_v[t*128+j] = v;
}

// ---------------- tail: attention + out proj + MLP + residual + LN + ReLU (fused) ----------------
__global__ void __launch_bounds__(256) k_tail3(const float* __restrict__ Wo, const float* __restrict__ bo,
                                               const float* __restrict__ Wm1, const float* __restrict__ bm1,
                                               const float* __restrict__ Wm2, const float* __restrict__ bm2,
                                               const float* __restrict__ g2, const float* __restrict__ beta2){
    __shared__ float ksh[32*128];
    __shared__ float vsh[32*128];
    __shared__ float qsh[128];
    __shared__ float osh[128];
    __shared__ float ash[8*32];
    __shared__ float xat[128];
    __shared__ float hid[HD2];
    __shared__ float red[128];
    __shared__ float pp[256];
    int t = blockIdx.x, tid = threadIdx.x;

    // --- attention ---
    for (int i = tid; i < 4096; i += 256){ ksh[i] = g_k[i]; vsh[i] = g_v[i]; }
    if (tid < 128) qsh[tid] = g_q[t*128+tid];
    __syncthreads();
    int h = tid >> 5, lane = tid & 31;
    float sc = 0.f;
    const float* qp = qsh + h*16;
    const float* kp = ksh + lane*128 + h*16;
    #pragma unroll
    for (int dd = 0; dd < 16; dd++) sc += qp[dd]*kp[dd];
    sc *= 0.25f;   // 1/sqrt(16)
    float m = sc;
    #pragma unroll
    for (int off = 16; off > 0; off >>= 1) m = fmaxf(m, __shfl_xor_sync(0xffffffffu, m, off));
    float e = __expf(sc - m);
    float sm = e;
    #pragma unroll
    for (int off = 16; off > 0; off >>= 1) sm += __shfl_xor_sync(0xffffffffu, sm, off);
    ash[h*32+lane] = e / sm;
    __syncwarp();
    if (lane < 16){
        float o = 0.f;
        #pragma unroll 4
        for (int s = 0; s < 32; s++) o += ash[h*32+s] * vsh[s*128 + h*16 + lane];
        osh[h*16+lane] = o;
    }
    __syncthreads();
    if (tid < 128){
        float xa = bo[tid];
        #pragma unroll 4
        for (int i = 0; i < 128; i++) xa = fmaf(osh[i], Wo[i*128+tid], xa);
        xat[tid] = xa;
    }
    __syncthreads();

    // --- MLP layer 1 (relu) ---
    for (int mm = tid; mm < HD2; mm += 256){
        float hh = bm1[mm];
        #pragma unroll 4
        for (int j = 0; j < 128; j++) hh = fmaf(xat[j], Wm1[j*HD2+mm], hh);
        hid[mm] = fmaxf(hh, 0.f);
    }
    __syncthreads();

    // --- MLP layer 2 (split over 2 thread-halves) + residual + LN + ReLU ---
    int j = tid & 127, hf = tid >> 7;
    float part = 0.f;
    #pragma unroll 4
    for (int mm = hf*256; mm < hf*256 + 256; mm++) part = fmaf(hid[mm], Wm2[mm*128+j], part);
    pp[tid] = part; __syncthreads();
    float y = 0.f;
    if (tid < 128){ y = pp[tid] + pp[tid+128] + bm2[tid] + xat[tid]; red[tid] = y; }
    __syncthreads();
    #pragma unroll
    for (int off = 64; off > 0; off >>= 1){ if (tid < off) red[tid] += red[tid+off]; __syncthreads(); }
    float mu = red[0] * (1.f/128.f);
    __syncthreads();
    float dv = y - mu;
    if (tid < 128) red[tid] = dv*dv;
    __syncthreads();
    #pragma unroll
    for (int off = 64; off > 0; off >>= 1){ if (tid < off) red[tid] += red[tid+off]; __syncthreads(); }
    float var = red[0] * (1.f/128.f);
    if (tid < 128){
        float yn = dv * rsqrtf(var + 1e-5f) * g2[tid] + beta2[tid];
        g_yr[t*128+tid] = fmaxf(yn, 0.f);
    }
}

// ---------------- tail: pool over T + final linear ----------------
__global__ void __launch_bounds__(128) k_final(const float* __restrict__ Wl, const float* __restrict__ bl,
                                               float* __restrict__ out){
    __shared__ float ps[128];
    int j = threadIdx.x;
    float s = 0.f;
    #pragma unroll
    for (int t = 0; t < TT; t++) s += g_yr[t*128+j];
    ps[j] = s; __syncthreads();
    if (j < CC){
        float o = bl[j];
        #pragma unroll 4
        for (int f = 0; f < 128; f++) o = fmaf(ps[f], Wl[f*CC+j], o);
        out[j] = o;
    }
}

// ---------------- launch ----------------
extern "C" void kernel_launch(void* const* d_in, const int* in_sizes, int n_in,
                              void* d_out, int out_size) {
    const float* x   = (const float*)d_in[0];
    const int*   ei  = (const int*)  d_in[1];
    const float* W0  = (const float*)d_in[2];  const float* b0 = (const float*)d_in[3];
    const float* W1  = (const float*)d_in[4];  const float* b1 = (const float*)d_in[5];
    const float* W2  = (const float*)d_in[6];  const float* b2 = (const float*)d_in[7];
    const float* Wq  = (const float*)d_in[8];  const float* bq = (const float*)d_in[9];
    const float* Wk  = (const float*)d_in[10]; const float* bk = (const float*)d_in[11];
    const float* Wv  = (const float*)d_in[12]; const float* bv = (const float*)d_in[13];
    const float* Wo  = (const float*)d_in[14]; const float* bo = (const float*)d_in[15];
    const float* g2  = (const float*)d_in[16]; const float* be2= (const float*)d_in[17];
    const float* Wm1 = (const float*)d_in[18]; const float* bm1= (const float*)d_in[19];
    const float* Wm2 = (const float*)d_in[20]; const float* bm2= (const float*)d_in[21];
    const float* Wl  = (const float*)d_in[22]; const float* bl = (const float*)d_in[23];
    float* out = (float*)d_out;

    const float* bs_[3] = {b0, b1, b2};

    cudaFuncSetAttribute(k_gemm_mma, cudaFuncAttributeMaxDynamicSharedMemorySize, GEMM_SMEM);

    k_count<<<(TT*EE)/256, 256>>>(ei, W0, W1, W2);
    k_scan<<<TT, 256>>>();
    k_sort<<<(TT*EE)/256, 256>>>(ei);

    for (int layer = 0; layer < 3; layer++){
        k_gemm_mma<<<NT/64, 256, GEMM_SMEM>>>(x, layer);
        k_gather<<<NT/8, 256>>>(bs_[layer]);
    }

    k_zpart<<<dim3(8, TT), 128>>>();
    k_qkv<<<TT, 128>>>(Wq, bq, Wk, bk, Wv, bv);
    k_tail3<<<TT, 256>>>(Wo, bo, Wm1, bm1, Wm2, bm2, g2, be2);
    k_final<<<1, 128>>>(Wl, bl, out);
}

// round 7
// speedup vs baseline: 1.0631x; 1.0006x over previous
#include <cuda_runtime.h>
#include <cuda_bf16.h>
#include <cstdint>

// Problem constants
#define TT   32
#define NN   5000
#define EE   80000
#define HH   128
#define HD2  512
#define CC   10
#define NT   (TT*NN)          // 160000 total nodes

// ---------------- device scratch (static; no allocation) ----------------
__device__ int   g_deg[NT];
__device__ float g_dinv[NT];
__device__ int   g_rowstart[TT*(NN+1)];
__device__ int   g_cursor[NT];
__device__ int   g_sorted[TT*EE];
__device__ float g_bufH[(size_t)NT*HH];   // h' = dinv * (x @ W)
__device__ float g_bufY[(size_t)NT*HH];   // layer output
__device__ __nv_bfloat16 g_Wh[3*16384];   // per-layer W hi
__device__ __nv_bfloat16 g_Wl[3*16384];   // per-layer W lo
__device__ float g_partial[TT*8*HH];
__device__ float g_q[TT*HH], g_k[TT*HH], g_v[TT*HH];
__device__ float g_yr[TT*HH];

__device__ __forceinline__ float4 ld4(const float* p){ return *reinterpret_cast<const float4*>(p); }
__device__ __forceinline__ float fast_tanh(float x){ asm("tanh.approx.f32 %0, %0;" : "+f"(x)); return x; }
__device__ __forceinline__ uint32_t smem_u32(const void* p){
    uint32_t a;
    asm("{ .reg .u64 t; cvta.to.shared.u64 t, %1; cvt.u32.u64 %0, t; }" : "=r"(a) : "l"(p));
    return a;
}
__device__ __forceinline__ uint32_t pack2(__nv_bfloat16 a, __nv_bfloat16 b){
    __nv_bfloat162 t = __halves2bfloat162(a, b);
    return *reinterpret_cast<uint32_t*>(&t);
}

#define LDSM_X4(r0,r1,r2,r3, addr) \
    asm volatile("ldmatrix.sync.aligned.m8n8.x4.shared.b16 {%0,%1,%2,%3}, [%4];" \
        : "=r"(r0),"=r"(r1),"=r"(r2),"=r"(r3) : "r"(addr))
#define LDSM_X4_T(r0,r1,r2,r3, addr) \
    asm volatile("ldmatrix.sync.aligned.m8n8.x4.trans.shared.b16 {%0,%1,%2,%3}, [%4];" \
        : "=r"(r0),"=r"(r1),"=r"(r2),"=r"(r3) : "r"(addr))
#define MMA16816(d, a, b) \
    asm volatile("mma.sync.aligned.m16n8k16.row.col.f32.bf16.bf16.f32 " \
        "{%0,%1,%2,%3}, {%4,%5,%6,%7}, {%8,%9}, {%0,%1,%2,%3};" \
        : "+f"((d)[0]),"+f"((d)[1]),"+f"((d)[2]),"+f"((d)[3]) \
        : "r"((a)[0]),"r"((a)[1]),"r"((a)[2]),"r"((a)[3]), "r"((b)[0]),"r"((b)[1]))

// ---------------- setup kernels ----------------
// precompute W hi/lo bf16 for all 3 layers (also shifts profile slot -> gather)
__global__ void k_wconv(const float* __restrict__ W0, const float* __restrict__ W1,
                        const float* __restrict__ W2){
    int i = blockIdx.x*256 + threadIdx.x;   // exact grid 3*16384
    int l = i >> 14, j = i & 16383;
    const float* Wp = (l == 0) ? W0 : ((l == 1) ? W1 : W2);
    float w = Wp[j];
    __nv_bfloat16 h = __float2bfloat16(w);
    g_Wh[i] = h;
    g_Wl[i] = __float2bfloat16(w - __bfloat162float(h));
}

// count degrees: 4 edges/thread (int4), 4 outstanding REDs
__global__ void k_count(const int* __restrict__ ei){
    int i = blockIdx.x*256 + threadIdx.x;      // exact grid TT*EE/4
    int e4 = i*4;
    int t = e4 / EE, e = e4 - t*EE;
    int4 d = *reinterpret_cast<const int4*>(ei + (size_t)t*2*EE + EE + e);
    int* deg = g_deg + t*NN;
    atomicAdd(&deg[d.x], 1);
    atomicAdd(&deg[d.y], 1);
    atomicAdd(&deg[d.z], 1);
    atomicAdd(&deg[d.w], 1);
}

// prefix-sum degrees into CSR rowstarts (warp-shuffle scan); zero g_deg for replay
__global__ void __launch_bounds__(256) k_scan(){
    int t = blockIdx.x, tid = threadIdx.x, lane = tid & 31, w = tid >> 5;
    __shared__ int wsum[8];
    __shared__ int sbase;
    if (tid == 0) sbase = 0;
    __syncthreads();
    for (int c = 0; c < 20; c++){
        int idx = c*256 + tid;
        int cnt = 0;
        if (idx < NN){
            cnt = g_deg[t*NN+idx];
            g_deg[t*NN+idx] = 0;       // reset for next replay
        }
        int v = cnt;
        #pragma unroll
        for (int off = 1; off < 32; off <<= 1){
            int u = __shfl_up_sync(0xffffffffu, v, off);
            if (lane >= off) v += u;
        }
        if (lane == 31) wsum[w] = v;
        __syncthreads();
        int woff = 0;
        #pragma unroll
        for (int k = 0; k < 8; k++) woff += (k < w) ? wsum[k] : 0;
        int base = sbase;
        int incl = v + woff;
        if (idx < NN){
            int ex = base + incl - cnt;
            g_rowstart[t*(NN+1)+idx] = ex;
            g_cursor[t*NN+idx] = ex;
            g_dinv[t*NN+idx] = rsqrtf((float)(cnt + 1));
        }
        __syncthreads();
        if (tid == 255) sbase = base + incl;   // total after this chunk
        __syncthreads();
    }
    if (tid == 0) g_rowstart[t*(NN+1)+NN] = sbase;  // == EE
}

// CSR bucket fill: 4 edges/thread (int4 src+dst), 4 outstanding atomic returns
__global__ void k_sort(const int* __restrict__ ei){
    int i = blockIdx.x*256 + threadIdx.x;      // exact grid TT*EE/4
    int e4 = i*4;
    int t = e4 / EE, e = e4 - t*EE;
    const int* base = ei + (size_t)t*2*EE;
    int4 s = *reinterpret_cast<const int4*>(base + e);
    int4 d = *reinterpret_cast<const int4*>(base + EE + e);
    int* cur = g_cursor + t*NN;
    int* out = g_sorted + t*EE;
    int p0 = atomicAdd(&cur[d.x], 1);
    int p1 = atomicAdd(&cur[d.y], 1);
    int p2 = atomicAdd(&cur[d.z], 1);
    int p3 = atomicAdd(&cur[d.w], 1);
    out[p0] = s.x; out[p1] = s.y; out[p2] = s.z; out[p3] = s.w;
}

// ---------------- tensor-core GEMM: h' = dinv * (X @ W) ----------------
// mma.sync m16n8k16 bf16, hi/lo split: D = Ah*Bh + Al*Bh + Ah*Bl.
// BM=64 tile -> 104.4KB smem -> 2 CTAs/SM.
#define PADW 136
#define GEMM_SMEM ((2*64*PADW + 2*128*PADW)*2)

__global__ void __launch_bounds__(256, 2) k_gemm_mma(const float* __restrict__ X0,
                                                     int layer){
    extern __shared__ __align__(16) char sm_[];
    __nv_bfloat16* Ah = (__nv_bfloat16*)sm_;
    __nv_bfloat16* Al = Ah + 64*PADW;
    __nv_bfloat16* Bh = Al + 64*PADW;
    __nv_bfloat16* Bl = Bh + 128*PADW;
    const float* __restrict__ X = (layer == 0) ? X0 : g_bufY;
    const int tid = threadIdx.x, wid = tid >> 5, lane = tid & 31;
    const int bm = blockIdx.x * 64;

    // ---- fill B from precomputed bf16 hi/lo (pure copy, 16B stores) ----
    {
        const uint4* wh = reinterpret_cast<const uint4*>(g_Wh + layer*16384);
        const uint4* wl = reinterpret_cast<const uint4*>(g_Wl + layer*16384);
        #pragma unroll
        for (int i = 0; i < 8; i++){
            int u   = tid + i*256;            // 0..2047 (each = 8 bf16)
            int row = u >> 4;                 // 0..127
            int c0  = (u & 15) << 3;          // 0..120
            int s = row*PADW + c0;
            *reinterpret_cast<uint4*>(Bh + s) = wh[u];
            *reinterpret_cast<uint4*>(Bl + s) = wl[u];
        }
    }
    // ---- fill A (X rows bm..bm+63) as hi/lo bf16 ----
    #pragma unroll
    for (int i = 0; i < 8; i++){
        int idx4 = tid + i*256;              // 0..2047
        int row  = idx4 >> 5;                // 0..63
        int c0   = (idx4 & 31) << 2;         // 0..124
        float4 v = ld4(X + (size_t)(bm + row)*128 + c0);
        __nv_bfloat16 ah0 = __float2bfloat16(v.x), ah1 = __float2bfloat16(v.y);
        __nv_bfloat16 ah2 = __float2bfloat16(v.z), ah3 = __float2bfloat16(v.w);
        uint2 avh, avl;
        avh.x = pack2(ah0, ah1); avh.y = pack2(ah2, ah3);
        avl.x = pack2(__float2bfloat16(v.x - __bfloat162float(ah0)),
                      __float2bfloat16(v.y - __bfloat162float(ah1)));
        avl.y = pack2(__float2bfloat16(v.z - __bfloat162float(ah2)),
                      __float2bfloat16(v.w - __bfloat162float(ah3)));
        int s = row*PADW + c0;
        *reinterpret_cast<uint2*>(Ah + s) = avh;
        *reinterpret_cast<uint2*>(Al + s) = avl;
    }
    __syncthreads();

    const int wr = (wid & 1) * 32;           // warp row base (0/32)
    const int wc = (wid >> 1) * 32;          // warp col base (0..96)
    const int lhalf = (lane >> 4) << 3;

    const uint32_t aBaseH = smem_u32(Ah) + (uint32_t)(((wr + (lane & 15))*PADW + lhalf) * 2);
    const uint32_t aBaseL = aBaseH + (uint32_t)(64*PADW*2);
    const uint32_t bBaseH = smem_u32(Bh) + (uint32_t)(((lane & 15)*PADW + wc + lhalf) * 2);
    const uint32_t bBaseL = bBaseH + (uint32_t)(128*PADW*2);

    float acc[2][4][4];
    #pragma unroll
    for (int mt = 0; mt < 2; mt++)
        #pragma unroll
        for (int nt = 0; nt < 4; nt++)
            #pragma unroll
            for (int c = 0; c < 4; c++) acc[mt][nt][c] = 0.f;

    #pragma unroll
    for (int ks = 0; ks < 8; ks++){
        const uint32_t k0b  = (uint32_t)(ks*16*2);
        const uint32_t k0rb = (uint32_t)(ks*16*PADW*2);
        uint32_t ah[2][4], al[2][4], bh[4][2], bl[4][2];
        #pragma unroll
        for (int mt = 0; mt < 2; mt++){
            uint32_t aH = aBaseH + (uint32_t)(mt*16*PADW*2) + k0b;
            uint32_t aL = aBaseL + (uint32_t)(mt*16*PADW*2) + k0b;
            LDSM_X4(ah[mt][0], ah[mt][1], ah[mt][2], ah[mt][3], aH);
            LDSM_X4(al[mt][0], al[mt][1], al[mt][2], al[mt][3], aL);
        }
        #pragma unroll
        for (int p = 0; p < 2; p++){
            uint32_t bH = bBaseH + k0rb + (uint32_t)(p*16*2);
            uint32_t bL = bBaseL + k0rb + (uint32_t)(p*16*2);
            LDSM_X4_T(bh[2*p][0], bh[2*p][1], bh[2*p+1][0], bh[2*p+1][1], bH);
            LDSM_X4_T(bl[2*p][0], bl[2*p][1], bl[2*p+1][0], bl[2*p+1][1], bL);
        }
        #pragma unroll
        for (int mt = 0; mt < 2; mt++)
            #pragma unroll
            for (int nt = 0; nt < 4; nt++){
                MMA16816(acc[mt][nt], ah[mt], bh[nt]);
                MMA16816(acc[mt][nt], al[mt], bh[nt]);
                MMA16816(acc[mt][nt], ah[mt], bl[nt]);
            }
    }

    // ---- epilogue: scale by dinv[row], store fp32 ----
    const int lr = lane >> 2, lq = lane & 3;
    #pragma unroll
    for (int mt = 0; mt < 2; mt++){
        int r0 = bm + wr + mt*16 + lr;
        float s0 = g_dinv[r0], s1 = g_dinv[r0 + 8];
        float* p0 = g_bufH + (size_t)r0*128 + wc + lq*2;
        float* p1 = p0 + (size_t)8*128;
        #pragma unroll
        for (int nt = 0; nt < 4; nt++){
            float2 v0 = make_float2(acc[mt][nt][0]*s0, acc[mt][nt][1]*s0);
            float2 v1 = make_float2(acc[mt][nt][2]*s1, acc[mt][nt][3]*s1);
            *reinterpret_cast<float2*>(p0 + nt*8) = v0;
            *reinterpret_cast<float2*>(p1 + nt*8) = v1;
        }
    }
}

// ---------------- gather: out[d] = tanh(dinv[d]*(h'[d] + sum h'[s]) + b) ----------------
#define ADD4(A, V) { A.x += V.x; A.y += V.y; A.z += V.z; A.w += V.w; }

__global__ void __launch_bounds__(256) k_gather(const float* __restrict__ bias){
    int warp = threadIdx.x >> 5, lane = threadIdx.x & 31;
    int g = blockIdx.x*8 + warp;      // grid exact: 20000*8 = 160000
    int t = g / NN, d = g - t*NN;
    const float* hb = g_bufH + (size_t)t*NN*128;
    int f4 = lane*4;

    float4 a0 = ld4(hb + (size_t)d*128 + f4);   // self loop
    float4 a1 = make_float4(0.f,0.f,0.f,0.f);
    float4 a2 = make_float4(0.f,0.f,0.f,0.f);
    float4 a3 = make_float4(0.f,0.f,0.f,0.f);
    int beg = g_rowstart[t*(NN+1)+d], end = g_rowstart[t*(NN+1)+d+1];
    const int* ss = g_sorted + t*EE;
    for (int j = beg; j < end; j += 32){
        int idx = j + lane;
        int sv = (idx < end) ? ss[idx] : 0;
        int cnt = min(32, end - j);
        int kk = 0;
        for (; kk + 4 <= cnt; kk += 4){
            int s0 = __shfl_sync(0xffffffffu, sv, kk);
            int s1 = __shfl_sync(0xffffffffu, sv, kk+1);
            int s2 = __shfl_sync(0xffffffffu, sv, kk+2);
            int s3 = __shfl_sync(0xffffffffu, sv, kk+3);
            float4 v0 = ld4(hb + (size_t)s0*128 + f4);
            float4 v1 = ld4(hb + (size_t)s1*128 + f4);
            float4 v2 = ld4(hb + (size_t)s2*128 + f4);
            float4 v3 = ld4(hb + (size_t)s3*128 + f4);
            ADD4(a0, v0); ADD4(a1, v1); ADD4(a2, v2); ADD4(a3, v3);
        }
        for (; kk < cnt; kk++){
            int s0 = __shfl_sync(0xffffffffu, sv, kk);
            float4 v0 = ld4(hb + (size_t)s0*128 + f4);
            ADD4(a0, v0);
        }
    }
    float sc = g_dinv[g];
    float4 bb = ld4(bias + f4);
    float4 r;
    r.x = fast_tanh(fmaf(sc, (a0.x + a1.x) + (a2.x + a3.x), bb.x));
    r.y = fast_tanh(fmaf(sc, (a0.y + a1.y) + (a2.y + a3.y), bb.y));
    r.z = fast_tanh(fmaf(sc, (a0.z + a1.z) + (a2.z + a3.z), bb.z));
    r.w = fast_tanh(fmaf(sc, (a0.w + a1.w) + (a2.w + a3.w), bb.w));
    *reinterpret_cast<float4*>(g_bufY + (size_t)g*128 + f4) = r;
}

// ---------------- z = sum over nodes (deterministic two-stage) ----------------
__global__ void __launch_bounds__(128) k_zpart(){
    int t = blockIdx.y, p = blockIdx.x, j = threadIdx.x;
    const float* base = g_bufY + ((size_t)t*NN + p*625)*128 + j;
    float s0=0.f, s1=0.f, s2=0.f, s3=0.f;
    int n = 0;
    for (; n + 4 <= 624; n += 4){
        s0 += base[(size_t)(n+0)*128];
        s1 += base[(size_t)(n+1)*128];
        s2 += base[(size_t)(n+2)*128];
        s3 += base[(size_t)(n+3)*128];
    }
    for (; n < 625; n++) s0 += base[(size_t)n*128];
    g_partial[(t*8+p)*128 + j] = (s0+s1) + (s2+s3);
}

// ---------------- tail: qkv ----------------
__global__ void __launch_bounds__(128) k_qkv(const float* __restrict__ Wq, const float* __restrict__ bq,
                                             const float* __restrict__ Wk, const float* __restrict__ bk,
                                             const float* __restrict__ Wv, const float* __restrict__ bv){
    __shared__ float zs[128];
    int t = blockIdx.x, j = threadIdx.x;
    float zsum = 0.f;
    #pragma unroll
    for (int p = 0; p < 8; p++) zsum += g_partial[(t*8+p)*128 + j];
    zs[j] = zsum; __syncthreads();
    float q = bq[j], k = bk[j], v = bv[j];
    #pragma unroll 4
    for (int i = 0; i < 128; i++){
        float zi = zs[i];
        q = fmaf(zi, Wq[i*128+j], q);
        k = fmaf(zi, Wk[i*128+j], k);
        v = fmaf(zi, Wv[i*128+j], v);
    }
    g_q[t*128+j] = q; g_k[t*128+j] = k; g_v[t*128+j] = v;
}

// ---------------- tail: attention + out proj + MLP + residual + LN + ReLU (fused) ----------------
__global__ void __launch_bounds__(256) k_tail3(const float* __restrict__ Wo, const float* __restrict__ bo,
                                               const float* __restrict__ Wm1, const float* __restrict__ bm1,
                                               const float* __restrict__ Wm2, const float* __restrict__ bm2,
                                               const float* __restrict__ g2, const float* __restrict__ beta2){
    __shared__ float ksh[32*128];
    __shared__ float vsh[32*128];
    __shared__ float qsh[128];
    __shared__ float osh[128];
    __shared__ float ash[8*32];
    __shared__ float xat[128];
    __shared__ float hid[HD2];
    __shared__ float red[128];
    __shared__ float pp[256];
    int t = blockIdx.x, tid = threadIdx.x;

    // --- attention ---
    for (int i = tid; i < 4096; i += 256){ ksh[i] = g_k[i]; vsh[i] = g_v[i]; }
    if (tid < 128) qsh[tid] = g_q[t*128+tid];
    __syncthreads();
    int h = tid >> 5, lane = tid & 31;
    float sc = 0.f;
    const float* qp = qsh + h*16;
    const float* kp = ksh + lane*128 + h*16;
    #pragma unroll
    for (int dd = 0; dd < 16; dd++) sc += qp[dd]*kp[dd];
    sc *= 0.25f;   // 1/sqrt(16)
    float m = sc;
    #pragma unroll
    for (int off = 16; off > 0; off >>= 1) m = fmaxf(m, __shfl_xor_sync(0xffffffffu, m, off));
    float e = __expf(sc - m);
    float sm = e;
    #pragma unroll
    for (int off = 16; off > 0; off >>= 1) sm += __shfl_xor_sync(0xffffffffu, sm, off);
    ash[h*32+lane] = e / sm;
    __syncwarp();
    if (lane < 16){
        float o = 0.f;
        #pragma unroll 4
        for (int s = 0; s < 32; s++) o += ash[h*32+s] * vsh[s*128 + h*16 + lane];
        osh[h*16+lane] = o;
    }
    __syncthreads();
    if (tid < 128){
        float xa = bo[tid];
        #pragma unroll 4
        for (int i = 0; i < 128; i++) xa = fmaf(osh[i], Wo[i*128+tid], xa);
        xat[tid] = xa;
    }
    __syncthreads();

    // --- MLP layer 1 (relu) ---
    for (int mm = tid; mm < HD2; mm += 256){
        float hh = bm1[mm];
        #pragma unroll 4
        for (int j = 0; j < 128; j++) hh = fmaf(xat[j], Wm1[j*HD2+mm], hh);
        hid[mm] = fmaxf(hh, 0.f);
    }
    __syncthreads();

    // --- MLP layer 2 (split over 2 thread-halves) + residual + LN + ReLU ---
    int j = tid & 127, hf = tid >> 7;
    float part = 0.f;
    #pragma unroll 4
    for (int mm = hf*256; mm < hf*256 + 256; mm++) part = fmaf(hid[mm], Wm2[mm*128+j], part);
    pp[tid] = part; __syncthreads();
    float y = 0.f;
    if (tid < 128){ y = pp[tid] + pp[tid+128] + bm2[tid] + xat[tid]; red[tid] = y; }
    __syncthreads();
    #pragma unroll
    for (int off = 64; off > 0; off >>= 1){ if (tid < off) red[tid] += red[tid+off]; __syncthreads(); }
    float mu = red[0] * (1.f/128.f);
    __syncthreads();
    float dv = y - mu;
    if (tid < 128) red[tid] = dv*dv;
    __syncthreads();
    #pragma unroll
    for (int off = 64; off > 0; off >>= 1){ if (tid < off) red[tid] += red[tid+off]; __syncthreads(); }
    float var = red[0] * (1.f/128.f);
    if (tid < 128){
        float yn = dv * rsqrtf(var + 1e-5f) * g2[tid] + beta2[tid];
        g_yr[t*128+tid] = fmaxf(yn, 0.f);
    }
}

// ---------------- tail: pool over T + final linear ----------------
__global__ void __launch_bounds__(128) k_final(const float* __restrict__ Wl, const float* __restrict__ bl,
                                               float* __restrict__ out){
    __shared__ float ps[128];
    int j = threadIdx.x;
    float s = 0.f;
    #pragma unroll
    for (int t = 0; t < TT; t++) s += g_yr[t*128+j];
    ps[j] = s; __syncthreads();
    if (j < CC){
        float o = bl[j];
        #pragma unroll 4
        for (int f = 0; f < 128; f++) o = fmaf(ps[f], Wl[f*CC+j], o);
        out[j] = o;
    }
}

// ---------------- launch ----------------
extern "C" void kernel_launch(void* const* d_in, const int* in_sizes, int n_in,
                              void* d_out, int out_size) {
    const float* x   = (const float*)d_in[0];
    const int*   ei  = (const int*)  d_in[1];
    const float* W0  = (const float*)d_in[2];  const float* b0 = (const float*)d_in[3];
    const float* W1  = (const float*)d_in[4];  const float* b1 = (const float*)d_in[5];
    const float* W2  = (const float*)d_in[6];  const float* b2 = (const float*)d_in[7];
    const float* Wq  = (const float*)d_in[8];  const float* bq = (const float*)d_in[9];
    const float* Wk  = (const float*)d_in[10]; const float* bk = (const float*)d_in[11];
    const float* Wv  = (const float*)d_in[12]; const float* bv = (const float*)d_in[13];
    const float* Wo  = (const float*)d_in[14]; const float* bo = (const float*)d_in[15];
    const float* g2  = (const float*)d_in[16]; const float* be2= (const float*)d_in[17];
    const float* Wm1 = (const float*)d_in[18]; const float* bm1= (const float*)d_in[19];
    const float* Wm2 = (const float*)d_in[20]; const float* bm2= (const float*)d_in[21];
    const float* Wl  = (const float*)d_in[22]; const float* bl = (const float*)d_in[23];
    float* out = (float*)d_out;

    const float* bs_[3] = {b0, b1, b2};

    cudaFuncSetAttribute(k_gemm_mma, cudaFuncAttributeMaxDynamicSharedMemorySize, GEMM_SMEM);

    k_wconv<<<(3*16384)/256, 256>>>(W0, W1, W2);
    k_count<<<(TT*EE)/1024, 256>>>(ei);
    k_scan<<<TT, 256>>>();
    k_sort<<<(TT*EE)/1024, 256>>>(ei);

    for (int layer = 0; layer < 3; layer++){
        k_gemm_mma<<<NT/64, 256, GEMM_SMEM>>>(x, layer);
        k_gather<<<NT/8, 256>>>(bs_[layer]);
    }

    k_zpart<<<dim3(8, TT), 128>>>();
    k_qkv<<<TT, 128>>>(Wq, bq, Wk, bk, Wv, bv);
    k_tail3<<<TT, 256>>>(Wo, bo, Wm1, bm1, Wm2, bm2, g2, be2);
    k_final<<<1, 128>>>(Wl, bl, out);
}